// round 8
// baseline (speedup 1.0000x reference)
#include <cuda_runtime.h>
#include <stdint.h>

// Problem shapes (fixed by the dataset)
#define B 32
#define T 8192
#define D 128
#define P 1024
#define WIN 8        // phonemes per block (one per warp)  — best config (R4)
#define THREADS 256

// ---------------------------------------------------------------------------
// R4 structure (grid 4096, 256 thr, 1 phoneme/warp) with a minimal scan
// epilogue: block `win` needs only phonemes [8*win, 8*win+8), whose scan
// state lives in threads 2*win and 2*win+1. Those two threads publish packed
// (start<<4 | d) int4s through 32 bytes of smem; no 4KB tables.
// ---------------------------------------------------------------------------
__global__ void __launch_bounds__(THREADS) fused_kernel(
    const float* __restrict__ mel,
    const int*   __restrict__ dur,
    float*       __restrict__ out)
{
    __shared__ int4 s_seg[2];                // packed segs for this block's 8 phonemes
    __shared__ int  s_wsum[THREADS / 32];

    const int b    = blockIdx.x >> 7;        // 128 windows per batch
    const int win  = blockIdx.x & 127;
    const int t    = threadIdx.x;
    const int lane = t & 31;
    const int wid  = t >> 5;

    // --- durations: thread t owns elements [4t, 4t+4) ---
    const int4 dv = reinterpret_cast<const int4*>(dur + b * P)[t];
    const int tsum = dv.x + dv.y + dv.z + dv.w;

    // --- warp inclusive scan of per-thread group sums ---
    int x = tsum;
    #pragma unroll
    for (int off = 1; off < 32; off <<= 1) {
        int y = __shfl_up_sync(0xFFFFFFFFu, x, off);
        if (lane >= off) x += y;
    }
    if (lane == 31) s_wsum[wid] = x;
    __syncthreads();

    // --- warp 0 exclusive-scans the 8 warp totals ---
    if (wid == 0) {
        int s  = (lane < THREADS / 32) ? s_wsum[lane] : 0;
        int tt = s;
        #pragma unroll
        for (int off = 1; off < THREADS / 32; off <<= 1) {
            int y = __shfl_up_sync(0xFFFFFFFFu, tt, off);
            if (lane >= off) tt += y;
        }
        if (lane < THREADS / 32) s_wsum[lane] = tt - s;
    }
    __syncthreads();

    // --- only the two owner threads publish their packed segments ---
    if ((t >> 1) == win) {                   // t == 2*win or 2*win+1
        int st = s_wsum[wid] + x - tsum;     // exclusive prefix before 4t
        int4 pk;
        pk.x = (st << 4) | dv.x;  st += dv.x;
        pk.y = (st << 4) | dv.y;  st += dv.y;
        pk.z = (st << 4) | dv.z;  st += dv.z;
        pk.w = (st << 4) | dv.w;
        s_seg[t & 1] = pk;
    }
    __syncthreads();

    // --- each warp gathers its phoneme p = win*8 + wid ---
    const int4 sg = s_seg[wid >> 2];
    const int sel = wid & 3;
    const int pk  = (sel == 0) ? sg.x : (sel == 1) ? sg.y : (sel == 2) ? sg.z : sg.w;
    const int d   = pk & 15;
    const int st  = pk >> 4;

    const float4* __restrict__ base =
        reinterpret_cast<const float4*>(mel + ((size_t)b * T + st) * D) + lane;

    float4 acc = make_float4(0.f, 0.f, 0.f, 0.f);
    #pragma unroll
    for (int f = 0; f < 8; ++f) {
        if (f < d) {
            float4 v = __ldcs(base + f * (D / 4));
            acc.x += v.x; acc.y += v.y; acc.z += v.z; acc.w += v.w;
        }
    }

    const float inv = (d > 0) ? (1.0f / (float)d) : 0.0f;
    acc.x *= inv; acc.y *= inv; acc.z *= inv; acc.w *= inv;

    const int p = win * WIN + wid;
    __stcs(reinterpret_cast<float4*>(out + ((size_t)b * P + p) * D) + lane, acc);
}

extern "C" void kernel_launch(void* const* d_in, const int* in_sizes, int n_in,
                              void* d_out, int out_size) {
    const float* mel = (const float*)d_in[0];
    const int*   dur = (const int*)d_in[1];
    float*       out = (float*)d_out;

    fused_kernel<<<(B * P) / WIN, THREADS>>>(mel, dur, out);
}

// round 9
// speedup vs baseline: 1.0225x; 1.0225x over previous
#include <cuda_runtime.h>
#include <stdint.h>

// Problem shapes (fixed by the dataset)
#define B 32
#define T 8192
#define D 128
#define P 1024
#define WIN 8
#define THREADS 256

// Packed per-phoneme segment: (start << 4) | duration   (start < 8192, d <= 8)
__device__ int g_seg[B * P];

// ---------------------------------------------------------------------------
// Kernel 1: scan. 32 blocks x 256 threads; thread t owns durations [4t,4t+4)
// of its batch. shfl warp scan + cross-warp pass, writes packed segs (int4).
// ---------------------------------------------------------------------------
__global__ void __launch_bounds__(THREADS) scan_kernel(const int* __restrict__ dur) {
    __shared__ int s_wsum[THREADS / 32];
    const int b    = blockIdx.x;
    const int t    = threadIdx.x;
    const int lane = t & 31;
    const int wid  = t >> 5;

    const int4 dv = reinterpret_cast<const int4*>(dur + b * P)[t];
    const int tsum = dv.x + dv.y + dv.z + dv.w;

    int x = tsum;
    #pragma unroll
    for (int off = 1; off < 32; off <<= 1) {
        int y = __shfl_up_sync(0xFFFFFFFFu, x, off);
        if (lane >= off) x += y;
    }
    if (lane == 31) s_wsum[wid] = x;
    __syncthreads();

    if (wid == 0) {
        int s  = (lane < THREADS / 32) ? s_wsum[lane] : 0;
        int tt = s;
        #pragma unroll
        for (int off = 1; off < THREADS / 32; off <<= 1) {
            int y = __shfl_up_sync(0xFFFFFFFFu, tt, off);
            if (lane >= off) tt += y;
        }
        if (lane < THREADS / 32) s_wsum[lane] = tt - s;
    }
    __syncthreads();

    int st = s_wsum[wid] + x - tsum;         // exclusive prefix before 4t
    int4 pk;
    pk.x = (st << 4) | dv.x;  st += dv.x;
    pk.y = (st << 4) | dv.y;  st += dv.y;
    pk.z = (st << 4) | dv.z;  st += dv.z;
    pk.w = (st << 4) | dv.w;
    reinterpret_cast<int4*>(g_seg + b * P)[t] = pk;
}

// ---------------------------------------------------------------------------
// Kernel 2: pure gather, launched with PDL. Blocks become resident during the
// scan and wait at cudaGridDependencySynchronize(); after release each warp
// does one packed-seg read + 8 predicated LDG.128 + 1 STG.128. No scan work.
// ---------------------------------------------------------------------------
__global__ void __launch_bounds__(THREADS) avg_kernel(
    const float* __restrict__ mel,
    float*       __restrict__ out)
{
    const int wid  = threadIdx.x >> 5;
    const int lane = threadIdx.x & 31;
    const int b    = blockIdx.x >> 7;        // 128 windows per batch
    const int win  = blockIdx.x & 127;
    const int p    = win * WIN + wid;

    // Wait for scan kernel's writes to be visible (PDL release).
    cudaGridDependencySynchronize();

    const int pk = g_seg[b * P + p];
    const int d  = pk & 15;
    const int st = pk >> 4;

    const float4* __restrict__ base =
        reinterpret_cast<const float4*>(mel + ((size_t)b * T + st) * D) + lane;

    float4 acc = make_float4(0.f, 0.f, 0.f, 0.f);
    #pragma unroll
    for (int f = 0; f < 8; ++f) {
        if (f < d) {
            float4 v = __ldcs(base + f * (D / 4));
            acc.x += v.x; acc.y += v.y; acc.z += v.z; acc.w += v.w;
        }
    }

    const float inv = (d > 0) ? (1.0f / (float)d) : 0.0f;
    acc.x *= inv; acc.y *= inv; acc.z *= inv; acc.w *= inv;

    __stcs(reinterpret_cast<float4*>(out + ((size_t)b * P + p) * D) + lane, acc);
}

extern "C" void kernel_launch(void* const* d_in, const int* in_sizes, int n_in,
                              void* d_out, int out_size) {
    const float* mel = (const float*)d_in[0];
    const int*   dur = (const int*)d_in[1];
    float*       out = (float*)d_out;

    scan_kernel<<<B, THREADS>>>(dur);

    cudaLaunchConfig_t cfg = {};
    cfg.gridDim  = dim3((B * P) / WIN, 1, 1);
    cfg.blockDim = dim3(THREADS, 1, 1);
    cudaLaunchAttribute attrs[1];
    attrs[0].id = cudaLaunchAttributeProgrammaticStreamSerialization;
    attrs[0].val.programmaticStreamSerializationAllowed = 1;
    cfg.attrs    = attrs;
    cfg.numAttrs = 1;
    cudaLaunchKernelEx(&cfg, avg_kernel, mel, out);
}